// round 3
// baseline (speedup 1.0000x reference)
#include <cuda_runtime.h>

// ---------------- problem constants ----------------
#define WS     12
#define NTOK   144            // WS*WS tokens per window
#define CH     192
#define NHEADS 6
#define HD     32
#define IMG    256
#define NWH    22             // windows per side (264/12)
#define NB     4
#define NWIN   (NB*NWH*NWH)   // 1936
#define XSTR   193            // smem stride for [144][192] tile (bank-safe)
#define QSTR   33             // smem stride for [144][32] tiles
#define SCALE  0.17677669529663687f   // 32^-0.5

typedef unsigned long long u64;

// ---------------- f32x2 packed-FMA helpers ----------------
__device__ __forceinline__ u64 pack2(float lo, float hi) {
    u64 r; asm("mov.b64 %0, {%1, %2};" : "=l"(r) : "f"(lo), "f"(hi)); return r;
}
__device__ __forceinline__ u64 dup2(float v) {
    u64 r; asm("mov.b64 %0, {%1, %1};" : "=l"(r) : "f"(v)); return r;
}
__device__ __forceinline__ void fma2(u64& d, u64 a, u64 b) {
    asm("fma.rn.f32x2 %0, %1, %2, %0;" : "+l"(d) : "l"(a), "l"(b));
}
__device__ __forceinline__ void unpack2(u64 v, float& lo, float& hi) {
    asm("mov.b64 {%0, %1}, %2;" : "=f"(lo), "=f"(hi) : "l"(v));
}

// =====================================================================
// Fully fused kernel: one block per window, 256 threads.
//   per head h:  QKV GEMM (K=192) -> coset attention -> attn-out to q_s
//                -> partial proj GEMM (K=32) into persistent registers
//   epilogue:    stage 144x192 result in x_s, scatter with crop.
// smem: x_s[144][193] + q/k/v_s[144][33]  = 168,192 B
// =====================================================================
__global__ void __launch_bounds__(256, 1)
wsa_fused(const float* __restrict__ x, const float* __restrict__ wqkv,
          const float* __restrict__ wproj, float* __restrict__ out) {
    extern __shared__ float smem[];
    float* x_s = smem;                     // 144*193
    float* q_s = smem + NTOK * XSTR;       // 144*33  (reused as attn-out slab)
    float* k_s = q_s + NTOK * QSTR;
    float* v_s = k_s + NTOK * QSTR;

    const int win = blockIdx.x;
    const int b   = win / (NWH * NWH);
    const int r0  = win % (NWH * NWH);
    const int wh  = r0 / NWH, ww = r0 % NWH;
    const int tid = threadIdx.x;

    // ---- stage window into smem with reflect padding ----
    const float* xb = x + (size_t)b * CH * IMG * IMG;
    for (int idx = tid; idx < NTOK * CH; idx += 256) {
        int c = idx / NTOK, n = idx % NTOK;
        int i = n / WS, j = n % WS;
        int ph = wh * WS + i; if (ph >= IMG) ph = 2 * IMG - 2 - ph;
        int pw = ww * WS + j; if (pw >= IMG) pw = 2 * IMG - 2 - pw;
        x_s[n * XSTR + c] = xb[(c * IMG + ph) * IMG + pw];
    }

    const int ty = tid >> 5;   // 0..7  -> row group (rows ty+16p, ty+16p+8)
    const int tx = tid & 31;   // 0..31 -> column within 32-wide group

    // persistent projection accumulators: rows (ty+16p, ty+16p+8), col tx+32s
    u64 acc[9][6];
    #pragma unroll
    for (int p = 0; p < 9; ++p)
        #pragma unroll
        for (int s = 0; s < 6; ++s) acc[p][s] = 0ULL;

    __syncthreads();

    for (int h = 0; h < NHEADS; ++h) {
        // ---------- QKV GEMM for this head: out[144][3*32], K=192 ----------
        const float* wq = wqkv + (size_t)(h * HD + tx) * CH;
        const float* wk = wq + 192 * CH;
        const float* wv = wk + 192 * CH;
        u64 aq[9], ak[9], av[9];
        #pragma unroll
        for (int p = 0; p < 9; ++p) { aq[p] = 0ULL; ak[p] = 0ULL; av[p] = 0ULL; }

        for (int c0 = 0; c0 < CH; c0 += 4) {
            float4 fq = *(const float4*)(wq + c0);
            float4 fk = *(const float4*)(wk + c0);
            float4 fv = *(const float4*)(wv + c0);
            const float* xc = x_s + c0;
            #pragma unroll
            for (int cc = 0; cc < 4; ++cc) {
                u64 bq = dup2(((const float*)&fq)[cc]);
                u64 bk = dup2(((const float*)&fk)[cc]);
                u64 bv = dup2(((const float*)&fv)[cc]);
                #pragma unroll
                for (int p = 0; p < 9; ++p) {
                    float x0 = xc[(ty + 16 * p) * XSTR + cc];
                    float x1 = xc[(ty + 16 * p + 8) * XSTR + cc];
                    u64 xa = pack2(x0, x1);
                    fma2(aq[p], xa, bq);
                    fma2(ak[p], xa, bk);
                    fma2(av[p], xa, bv);
                }
            }
        }
        #pragma unroll
        for (int p = 0; p < 9; ++p) {
            int n0 = ty + 16 * p, n1 = n0 + 8;
            float l, hgh;
            unpack2(aq[p], l, hgh); q_s[n0 * QSTR + tx] = l; q_s[n1 * QSTR + tx] = hgh;
            unpack2(ak[p], l, hgh); k_s[n0 * QSTR + tx] = l; k_s[n1 * QSTR + tx] = hgh;
            unpack2(av[p], l, hgh); v_s[n0 * QSTR + tx] = l; v_s[n1 * QSTR + tx] = hgh;
        }
        __syncthreads();

        // ---------- dilated coset attention (15 keys/query) ----------
        float o[HD]; float inv = 0.f;
        if (tid < NTOK) {
            const int qi = tid / WS, qj = tid % WS;
            const int ca = qi % 3, cb = qj % 3;
            float q[HD];
            #pragma unroll
            for (int dd = 0; dd < HD; ++dd) q[dd] = q_s[tid * QSTR + dd];

            float e[16];
            float mx = -1e30f;
            #pragma unroll
            for (int u = 0; u < 4; ++u) {
                #pragma unroll
                for (int v = 0; v < 4; ++v) {
                    int m = (ca + 3 * u) * WS + (cb + 3 * v);
                    float s = 0.f;
                    #pragma unroll
                    for (int dd = 0; dd < HD; ++dd) s += q[dd] * k_s[m * QSTR + dd];
                    s *= SCALE;
                    if (m == tid) s = -1e30f;    // self excluded
                    e[u * 4 + v] = s;
                    mx = fmaxf(mx, s);
                }
            }
            float den = 0.f;
            #pragma unroll
            for (int t = 0; t < 16; ++t) { e[t] = __expf(e[t] - mx); den += e[t]; }
            inv = 1.0f / den;

            #pragma unroll
            for (int dd = 0; dd < HD; ++dd) o[dd] = 0.f;
            #pragma unroll
            for (int t = 0; t < 16; ++t) {
                int m = (ca + 3 * (t >> 2)) * WS + (cb + 3 * (t & 3));
                float p = e[t];
                #pragma unroll
                for (int dd = 0; dd < HD; ++dd) o[dd] += p * v_s[m * QSTR + dd];
            }
        }
        __syncthreads();   // all q_s reads done before overwrite

        if (tid < NTOK) {
            #pragma unroll
            for (int dd = 0; dd < HD; ++dd) q_s[tid * QSTR + dd] = o[dd] * inv;
        }
        __syncthreads();

        // ---------- partial proj GEMM: out += attn_h[144x32] @ Wp_h[192x32]^T ----------
        const float* wp = wproj + (size_t)h * HD;   // col offset h*32 in [192][192]
        for (int c0 = 0; c0 < HD; c0 += 4) {
            float4 wv4[6];
            #pragma unroll
            for (int s = 0; s < 6; ++s)
                wv4[s] = *(const float4*)(wp + (size_t)(tx + 32 * s) * CH + c0);
            const float* ac = q_s + c0;
            #pragma unroll
            for (int cc = 0; cc < 4; ++cc) {
                u64 xa[9];
                #pragma unroll
                for (int p = 0; p < 9; ++p) {
                    float x0 = ac[(ty + 16 * p) * QSTR + cc];
                    float x1 = ac[(ty + 16 * p + 8) * QSTR + cc];
                    xa[p] = pack2(x0, x1);
                }
                #pragma unroll
                for (int s = 0; s < 6; ++s) {
                    u64 bw = dup2(((const float*)&wv4[s])[cc]);
                    #pragma unroll
                    for (int p = 0; p < 9; ++p) fma2(acc[p][s], xa[p], bw);
                }
            }
        }
        __syncthreads();   // proj reads of q_s done before next head's QKV writes
    }

    // ---------- epilogue: stage in x_s (free now), scatter with crop ----------
    #pragma unroll
    for (int p = 0; p < 9; ++p) {
        int n0 = ty + 16 * p, n1 = n0 + 8;
        #pragma unroll
        for (int s = 0; s < 6; ++s) {
            float l, hgh; unpack2(acc[p][s], l, hgh);
            x_s[n0 * XSTR + tx + 32 * s] = l;
            x_s[n1 * XSTR + tx + 32 * s] = hgh;
        }
    }
    __syncthreads();

    const int hbase = wh * WS, wbase = ww * WS;
    for (int idx = tid; idx < NTOK * CH; idx += 256) {
        int c = idx / NTOK, n = idx % NTOK;
        int i = n / WS, j = n % WS;
        int hh = hbase + i, w2 = wbase + j;
        if (hh < IMG && w2 < IMG)
            out[(((size_t)b * CH + c) * IMG + hh) * IMG + w2] = x_s[n * XSTR + c];
    }
}

// =====================================================================
// launch
// =====================================================================
extern "C" void kernel_launch(void* const* d_in, const int* in_sizes, int n_in,
                              void* d_out, int out_size) {
    (void)in_sizes; (void)n_in; (void)out_size;
    const float* x     = (const float*)d_in[0];
    const float* wqkv  = (const float*)d_in[1];
    const float* wproj = (const float*)d_in[2];
    float* out = (float*)d_out;

    const int smemA = (NTOK * XSTR + 3 * NTOK * QSTR) * (int)sizeof(float); // 168,192 B
    cudaFuncSetAttribute(wsa_fused, cudaFuncAttributeMaxDynamicSharedMemorySize, smemA);
    wsa_fused<<<NWIN, 256, smemA>>>(x, wqkv, wproj, out);
}

// round 4
// speedup vs baseline: 1.1705x; 1.1705x over previous
#include <cuda_runtime.h>

// ---------------- problem constants ----------------
#define WS     12
#define NTOK   144            // WS*WS tokens per window
#define CH     192
#define NHEADS 6
#define HD     32
#define IMG    256
#define NWH    22             // windows per side (264/12)
#define NB     4
#define NWIN   (NB*NWH*NWH)   // 1936
#define PSTR   144            // x_s pair-layout stride (floats per channel)
#define ESTR   145            // epilogue staging stride (bank-safe)
#define QSTR   36             // q/k/v row stride (float4-aligned, conflict-free STS)
#define SCALE  0.17677669529663687f   // 32^-0.5

typedef unsigned long long u64;

__device__ __forceinline__ u64 dup2(float v) {
    u64 r; asm("mov.b64 %0, {%1, %1};" : "=l"(r) : "f"(v)); return r;
}
__device__ __forceinline__ void fma2(u64& d, u64 a, u64 b) {
    asm("fma.rn.f32x2 %0, %1, %2, %0;" : "+l"(d) : "l"(a), "l"(b));
}
__device__ __forceinline__ void unpack2(u64 v, float& lo, float& hi) {
    asm("mov.b64 {%0, %1}, %2;" : "=f"(lo), "=f"(hi) : "l"(v));
}
__device__ __forceinline__ float f4e(const float4& f, int i) {
    return i == 0 ? f.x : (i == 1 ? f.y : (i == 2 ? f.z : f.w));
}

// =====================================================================
// Fully fused kernel: one block per window, 256 threads.
// x_s stored pair-interleaved per channel: col(n) = (n>>4)*16 + (n&7)*2 + ((n>>3)&1)
// so row-pairs (n, n+8) are adjacent -> LDS.64 feeds fma.rn.f32x2 directly.
// =====================================================================
__global__ void __launch_bounds__(256, 1)
wsa_fused(const float* __restrict__ x, const float* __restrict__ wqkv,
          const float* __restrict__ wproj, float* __restrict__ out) {
    extern __shared__ float smem[];
    float* x_s = smem;                       // 192*145 floats (PSTR layout + epilogue ESTR)
    float* q_s = smem + CH * ESTR;           // 144*36 (reused as ao_s pair-layout)
    float* k_s = q_s + NTOK * QSTR;
    float* v_s = k_s + NTOK * QSTR;
    float* ao_s = q_s;                       // [32][144] attn-out pair layout

    const int win = blockIdx.x;
    const int b   = win / (NWH * NWH);
    const int r0  = win % (NWH * NWH);
    const int wh  = r0 / NWH, ww = r0 % NWH;
    const int tid = threadIdx.x;

    // ---- stage window: reflect pad, write pair-interleaved layout ----
    const float* xb = x + (size_t)b * CH * IMG * IMG;
    for (int idx = tid; idx < NTOK * CH; idx += 256) {
        int c = idx / NTOK, n = idx % NTOK;
        int col = (n >> 4) * 16 + (n & 7) * 2 + ((n >> 3) & 1);
        int i = n / WS, j = n % WS;
        int ph = wh * WS + i; if (ph >= IMG) ph = 2 * IMG - 2 - ph;
        int pw = ww * WS + j; if (pw >= IMG) pw = 2 * IMG - 2 - pw;
        x_s[c * PSTR + col] = xb[(c * IMG + ph) * IMG + pw];
    }

    const int ty = tid >> 5;   // 0..7 : row-pair base (rows ty+16p, ty+16p+8)
    const int tx = tid & 31;   // 0..31: output column within 32-group

    u64 acc[9][6];             // persistent proj accumulators
    #pragma unroll
    for (int p = 0; p < 9; ++p)
        #pragma unroll
        for (int s = 0; s < 6; ++s) acc[p][s] = 0ULL;

    __syncthreads();

    for (int h = 0; h < NHEADS; ++h) {
        // ---------- QKV GEMM: out[144][3*32], K=192, prefetched weights ----------
        const float* wq = wqkv + (size_t)(h * HD + tx) * CH;
        const float* wk = wq + 192 * CH;
        const float* wv = wk + 192 * CH;
        u64 aq[9], ak[9], av[9];
        #pragma unroll
        for (int p = 0; p < 9; ++p) { aq[p] = 0ULL; ak[p] = 0ULL; av[p] = 0ULL; }

        float4 fq = *(const float4*)(wq);
        float4 fk = *(const float4*)(wk);
        float4 fv = *(const float4*)(wv);
        #pragma unroll 1
        for (int c0 = 0; c0 < CH; c0 += 4) {
            int c1 = c0 + 4; if (c1 == CH) c1 = 0;     // wrap: harmless dummy prefetch
            float4 nq = *(const float4*)(wq + c1);
            float4 nk = *(const float4*)(wk + c1);
            float4 nv = *(const float4*)(wv + c1);
            #pragma unroll
            for (int cc = 0; cc < 4; ++cc) {
                u64 bq = dup2(f4e(fq, cc));
                u64 bk = dup2(f4e(fk, cc));
                u64 bv = dup2(f4e(fv, cc));
                const float* xc = x_s + (c0 + cc) * PSTR + ty * 2;
                #pragma unroll
                for (int p = 0; p < 9; ++p) {
                    u64 xa = *(const u64*)(xc + p * 16);   // LDS.64: packed row pair
                    fma2(aq[p], xa, bq);
                    fma2(ak[p], xa, bk);
                    fma2(av[p], xa, bv);
                }
            }
            fq = nq; fk = nk; fv = nv;
        }
        #pragma unroll
        for (int p = 0; p < 9; ++p) {
            int n0 = ty + 16 * p, n1 = n0 + 8;
            float l, hh;
            unpack2(aq[p], l, hh); q_s[n0 * QSTR + tx] = l; q_s[n1 * QSTR + tx] = hh;
            unpack2(ak[p], l, hh); k_s[n0 * QSTR + tx] = l; k_s[n1 * QSTR + tx] = hh;
            unpack2(av[p], l, hh); v_s[n0 * QSTR + tx] = l; v_s[n1 * QSTR + tx] = hh;
        }
        __syncthreads();

        // ---------- dilated coset attention (15 keys/query), float4 LDS ----------
        float4 o4[8]; float inv = 0.f;
        if (tid < NTOK) {
            const int qi = tid / WS, qj = tid % WS;
            const int ca = qi % 3, cb = qj % 3;
            float4 q4[8];
            #pragma unroll
            for (int d4 = 0; d4 < 8; ++d4) q4[d4] = *(const float4*)(q_s + tid * QSTR + d4 * 4);

            float e[16], mx = -1e30f;
            #pragma unroll
            for (int u = 0; u < 4; ++u)
                #pragma unroll
                for (int v = 0; v < 4; ++v) {
                    int m = (ca + 3 * u) * WS + (cb + 3 * v);
                    float sx = 0.f, sy = 0.f, sz = 0.f, sw = 0.f;
                    #pragma unroll
                    for (int d4 = 0; d4 < 8; ++d4) {
                        float4 kk = *(const float4*)(k_s + m * QSTR + d4 * 4);
                        sx += q4[d4].x * kk.x; sy += q4[d4].y * kk.y;
                        sz += q4[d4].z * kk.z; sw += q4[d4].w * kk.w;
                    }
                    float s = ((sx + sy) + (sz + sw)) * SCALE;
                    if (m == tid) s = -1e30f;      // self excluded by mask
                    e[u * 4 + v] = s;
                    mx = fmaxf(mx, s);
                }
            float den = 0.f;
            #pragma unroll
            for (int t = 0; t < 16; ++t) { e[t] = __expf(e[t] - mx); den += e[t]; }
            inv = 1.0f / den;

            #pragma unroll
            for (int d4 = 0; d4 < 8; ++d4) o4[d4] = make_float4(0.f, 0.f, 0.f, 0.f);
            #pragma unroll
            for (int t = 0; t < 16; ++t) {
                int m = (ca + 3 * (t >> 2)) * WS + (cb + 3 * (t & 3));
                float p = e[t];
                #pragma unroll
                for (int d4 = 0; d4 < 8; ++d4) {
                    float4 vv = *(const float4*)(v_s + m * QSTR + d4 * 4);
                    o4[d4].x += p * vv.x; o4[d4].y += p * vv.y;
                    o4[d4].z += p * vv.z; o4[d4].w += p * vv.w;
                }
            }
        }
        __syncthreads();   // all q_s reads done before ao overwrite

        if (tid < NTOK) {
            int col = (tid >> 4) * 16 + (tid & 7) * 2 + ((tid >> 3) & 1);
            #pragma unroll
            for (int d4 = 0; d4 < 8; ++d4) {
                ao_s[(d4 * 4 + 0) * NTOK + col] = o4[d4].x * inv;
                ao_s[(d4 * 4 + 1) * NTOK + col] = o4[d4].y * inv;
                ao_s[(d4 * 4 + 2) * NTOK + col] = o4[d4].z * inv;
                ao_s[(d4 * 4 + 3) * NTOK + col] = o4[d4].w * inv;
            }
        }
        __syncthreads();

        // ---------- partial proj GEMM: acc += attn_h[144x32] @ Wp_h[:,h*32:+32]^T ----------
        const float* wp = wproj + (size_t)h * HD;
        float4 cw[6];
        #pragma unroll
        for (int s = 0; s < 6; ++s) cw[s] = *(const float4*)(wp + (size_t)(tx + 32 * s) * CH);
        #pragma unroll 1
        for (int c0 = 0; c0 < HD; c0 += 4) {
            int c1 = c0 + 4; if (c1 == HD) c1 = 0;
            float4 nw[6];
            #pragma unroll
            for (int s = 0; s < 6; ++s) nw[s] = *(const float4*)(wp + (size_t)(tx + 32 * s) * CH + c1);
            #pragma unroll
            for (int cc = 0; cc < 4; ++cc) {
                const float* ac = ao_s + (c0 + cc) * NTOK + ty * 2;
                u64 xa[9];
                #pragma unroll
                for (int p = 0; p < 9; ++p) xa[p] = *(const u64*)(ac + p * 16);
                #pragma unroll
                for (int s = 0; s < 6; ++s) {
                    u64 bw = dup2(f4e(cw[s], cc));
                    #pragma unroll
                    for (int p = 0; p < 9; ++p) fma2(acc[p][s], xa[p], bw);
                }
            }
            #pragma unroll
            for (int s = 0; s < 6; ++s) cw[s] = nw[s];
        }
        __syncthreads();   // proj reads of ao_s done before next head's qkv writes
    }

    // ---------- epilogue: stage channel-major (stride ESTR), scatter with crop ----------
    #pragma unroll
    for (int p = 0; p < 9; ++p) {
        int n0 = ty + 16 * p, n1 = n0 + 8;
        #pragma unroll
        for (int s = 0; s < 6; ++s) {
            float l, hh; unpack2(acc[p][s], l, hh);
            x_s[(tx + 32 * s) * ESTR + n0] = l;
            x_s[(tx + 32 * s) * ESTR + n1] = hh;
        }
    }
    __syncthreads();

    const int hbase = wh * WS, wbase = ww * WS;
    for (int idx = tid; idx < NTOK * CH; idx += 256) {
        int c = idx / NTOK, n = idx % NTOK;
        int i = n / WS, j = n % WS;
        int hh2 = hbase + i, w2 = wbase + j;
        if (hh2 < IMG && w2 < IMG)
            out[(((size_t)b * CH + c) * IMG + hh2) * IMG + w2] = x_s[c * ESTR + n];
    }
}

// =====================================================================
// launch
// =====================================================================
extern "C" void kernel_launch(void* const* d_in, const int* in_sizes, int n_in,
                              void* d_out, int out_size) {
    (void)in_sizes; (void)n_in; (void)out_size;
    const float* x     = (const float*)d_in[0];
    const float* wqkv  = (const float*)d_in[1];
    const float* wproj = (const float*)d_in[2];
    float* out = (float*)d_out;

    const int smemA = (CH * ESTR + 3 * NTOK * QSTR) * (int)sizeof(float); // 173,568 B
    cudaFuncSetAttribute(wsa_fused, cudaFuncAttributeMaxDynamicSharedMemorySize, smemA);
    wsa_fused<<<NWIN, 256, smemA>>>(x, wqkv, wproj, out);
}